// round 14
// baseline (speedup 1.0000x reference)
#include <cuda_runtime.h>
#include <cuda_bf16.h>
#include <cstdint>

#define T_STEPS 28
#define HID 128
#define IND 28
#define NCLS 10
#define BATCH 8192

typedef unsigned long long u64;

// 112 MB scratch: layer-0 input GEMM (+ fused biases), layout [b*T+t][c]
__device__ float g_xw0[BATCH * T_STEPS * HID];

// ---------------- packed fp32x2 helpers ----------------
#define FMA2(acc, a, b) \
    asm("fma.rn.f32x2 %0, %1, %2, %0;" : "+l"(acc) : "l"(a), "l"(b))
#define DUP2(d, s) \
    asm("mov.b64 %0, {%1, %1};" : "=l"(d) : "f"(s))
#define LDS2(a, b, addr) \
    asm("ld.shared.v2.u64 {%0, %1}, [%2];" : "=l"(a), "=l"(b) : "r"(addr))
#define STG2(p, a, b) \
    asm("st.global.v2.u64 [%0], {%1, %2};" :: "l"(p), "l"(a), "l"(b))

__device__ __forceinline__ float ftanh(float x) {
    float e = __expf(2.0f * x);
    return 1.0f - __fdividef(2.0f, e + 1.0f);
}
__device__ __forceinline__ unsigned smaddr(const void* p) {
    return (unsigned)__cvta_generic_to_shared(p);
}

// ---------------- mma.sync helpers ----------------
__device__ __forceinline__ void ldsm4(uint32_t* r, uint32_t a) {
    asm volatile("ldmatrix.sync.aligned.m8n8.x4.shared.b16 {%0,%1,%2,%3}, [%4];"
                 : "=r"(r[0]), "=r"(r[1]), "=r"(r[2]), "=r"(r[3]) : "r"(a));
}
__device__ __forceinline__ void mma16816(float* d, const uint32_t* a,
                                         uint32_t b0, uint32_t b1) {
    asm volatile("mma.sync.aligned.m16n8k16.row.col.f32.bf16.bf16.f32 "
                 "{%0,%1,%2,%3}, {%4,%5,%6,%7}, {%8,%9}, {%0,%1,%2,%3};"
                 : "+f"(d[0]), "+f"(d[1]), "+f"(d[2]), "+f"(d[3])
                 : "r"(a[0]), "r"(a[1]), "r"(a[2]), "r"(a[3]), "r"(b0), "r"(b1));
}
__device__ __forceinline__ uint32_t pack2(float v0, float v1) {
    uint32_t r;
    asm("cvt.rn.bf16x2.f32 %0, %1, %2;" : "=r"(r) : "f"(v1), "f"(v0));
    return r;
}
__device__ __forceinline__ void cvt_pair(float v0, float v1,
                                         uint32_t& hi, uint32_t& lo) {
    uint32_t hp = pack2(v0, v1);
    float e0 = __uint_as_float(hp << 16);
    float e1 = __uint_as_float(hp & 0xffff0000u);
    hi = hp;
    lo = pack2(v0 - e0, v1 - e1);
}
#define STS32(a, v) asm volatile("st.shared.b32 [%0], %1;" :: "r"(a), "r"(v) : "memory")
#define BARQ(id) asm volatile("bar.sync %0, %1;" :: "r"(id), "r"(128) : "memory")
#define BART(id) asm volatile("bar.sync %0, %1;" :: "r"(id), "r"(256) : "memory")

// ---- weight tiles: [n][k] bf16, 128 rows x 256B, XOR-swizzled 16B chunks ----
#define WROWB 256
#define WTILE2 (128 * WROWB)          // 32768 B
#define SM_W   0                      // 6 tiles: W0h W0l W1h W1l W2h W2l
#define SM_HX  (6 * WTILE2)           // 196608: 4 quad bufs x 8192 (hi@0, lo@4096)
#define SM_B1  (SM_HX + 4 * 8192)     // 229376: 128 f32
#define SMEM_TOTAL (SM_B1 + 512)      // 229888

__device__ __forceinline__ uint32_t wtile_off2(int n, int k) {
    return (uint32_t)n * WROWB + ((((uint32_t)k >> 3) ^ ((uint32_t)n & 7)) << 4)
           + ((uint32_t)k & 7) * 2;
}

// quarter-N 3-term split-bf16 GEMM: d[4][4] += A(split) @ W_32col(split)^T.
__device__ __forceinline__ void gemm3q(float (*d)[4],
                                       uint32_t aHi, uint32_t aLo,
                                       uint32_t bHi, uint32_t bLo,
                                       int kbA, int kbB, int xr) {
#pragma unroll
    for (int s = 0; s < 8; s++) {
        const uint32_t aoff = (uint32_t)(((2 * s + kbA) ^ xr) << 4);
        const uint32_t boff = (uint32_t)(((2 * s + kbB) ^ xr) << 4);
        uint32_t ah[4], al[4], bh0[4], bh1[4], bl0[4], bl1[4];
        ldsm4(ah, aHi + aoff);
        ldsm4(al, aLo + aoff);
        ldsm4(bh0, bHi + boff);
        ldsm4(bh1, bHi + 4096 + boff);
        ldsm4(bl0, bLo + boff);
        ldsm4(bl1, bLo + 4096 + boff);
        mma16816(d[0], ah, bh0[0], bh0[1]);
        mma16816(d[1], ah, bh0[2], bh0[3]);
        mma16816(d[2], ah, bh1[0], bh1[1]);
        mma16816(d[3], ah, bh1[2], bh1[3]);
        mma16816(d[0], ah, bl0[0], bl0[1]);
        mma16816(d[1], ah, bl0[2], bl0[3]);
        mma16816(d[2], ah, bl1[0], bl1[1]);
        mma16816(d[3], ah, bl1[2], bl1[3]);
        mma16816(d[0], al, bh0[0], bh0[1]);
        mma16816(d[1], al, bh0[2], bh0[3]);
        mma16816(d[2], al, bh1[0], bh1[1]);
        mma16816(d[3], al, bh1[2], bh1[3]);
    }
}

// ---------------------------------------------------------------------------
// Single fused kernel: per-CTA xw0 precompute (FFMA2) + weight split +
// 28-step 2-layer recurrence (16 warps, quad-split N) + FC head.
// ---------------------------------------------------------------------------
__global__ __launch_bounds__(512, 1) void rnn_fused_kernel(
    const float* __restrict__ x,    const float* __restrict__ Wih0,
    const float* __restrict__ bih0, const float* __restrict__ bhh0,
    const float* __restrict__ Whh0, const float* __restrict__ Wih1,
    const float* __restrict__ Whh1, const float* __restrict__ bih1,
    const float* __restrict__ bhh1, const float* __restrict__ fcw,
    const float* __restrict__ fcb,  float* __restrict__ out)
{
    extern __shared__ char smem[];
    const int tid = threadIdx.x;
    const int wid = tid >> 5, lane = tid & 31;
    const int q = wid >> 2, u = wid & 3;

    // =========== PHASE 1: per-CTA input GEMM -> private g_xw0 slab =========
    {
        float* Wt  = (float*)(smem + SM_HX);            // 28x128 f32 (14336 B)
        float* xsT = (float*)(smem + SM_HX + 14336);    // 2 teams x 28x64 f32
        float* b0s = (float*)(smem + SM_B1);            // borrow b1 slot

        for (int idx = tid; idx < HID * IND; idx += 512) {
            int j = idx / IND, d = idx - j * IND;
            Wt[d * HID + j] = Wih0[idx];
        }
        if (tid < HID) b0s[tid] = bih0[tid] + bhh0[tid];
        __syncthreads();

        const int team = tid >> 8;            // 0/1 (warps 0-7 / 8-15)
        const int ttid = tid & 255;
        const int col0t = 16 * (wid & 7);
        const int r0t = 2 * lane;
        float* xs = xsT + team * 1792;
        const unsigned aW  = smaddr(Wt)  + col0t * 4;
        const unsigned aB0 = smaddr(b0s) + col0t * 4;
        const int tbar = 5 + team;
        const int bbase = blockIdx.x * 64 * T_STEPS;    // first flattened row

        for (int it = 0; it < 14; it++) {
            const int gr0 = bbase + (2 * it + team) * 64;
            for (int idx = ttid; idx < 64 * IND; idx += 256) {
                int r = idx / IND, d = idx - r * IND;
                xs[d * 64 + r] = x[(size_t)gr0 * IND + idx];  // rows contiguous
            }
            BART(tbar);

            u64 acc0[8], acc1[8];
            LDS2(acc0[0], acc0[1], aB0);
            LDS2(acc0[2], acc0[3], aB0 + 16);
            LDS2(acc0[4], acc0[5], aB0 + 32);
            LDS2(acc0[6], acc0[7], aB0 + 48);
#pragma unroll
            for (int j = 0; j < 8; j++) acc1[j] = acc0[j];

#pragma unroll
            for (int d = 0; d < IND; d++) {
                float2 hp = *(const float2*)&xs[d * 64 + r0t];
                u64 ha, hb; DUP2(ha, hp.x); DUP2(hb, hp.y);
                u64 w0, w1, w2, w3, w4, w5, w6, w7;
                LDS2(w0, w1, aW + d * 512);
                LDS2(w2, w3, aW + d * 512 + 16);
                LDS2(w4, w5, aW + d * 512 + 32);
                LDS2(w6, w7, aW + d * 512 + 48);
                FMA2(acc0[0], ha, w0); FMA2(acc0[1], ha, w1);
                FMA2(acc0[2], ha, w2); FMA2(acc0[3], ha, w3);
                FMA2(acc0[4], ha, w4); FMA2(acc0[5], ha, w5);
                FMA2(acc0[6], ha, w6); FMA2(acc0[7], ha, w7);
                FMA2(acc1[0], hb, w0); FMA2(acc1[1], hb, w1);
                FMA2(acc1[2], hb, w2); FMA2(acc1[3], hb, w3);
                FMA2(acc1[4], hb, w4); FMA2(acc1[5], hb, w5);
                FMA2(acc1[6], hb, w6); FMA2(acc1[7], hb, w7);
            }

            float* dst0 = &g_xw0[(size_t)(gr0 + r0t) * HID + col0t];
            float* dst1 = dst0 + HID;
            STG2((u64)dst0,      acc0[0], acc0[1]);
            STG2((u64)dst0 + 16, acc0[2], acc0[3]);
            STG2((u64)dst0 + 32, acc0[4], acc0[5]);
            STG2((u64)dst0 + 48, acc0[6], acc0[7]);
            STG2((u64)dst1,      acc1[0], acc1[1]);
            STG2((u64)dst1 + 16, acc1[2], acc1[3]);
            STG2((u64)dst1 + 32, acc1[4], acc1[5]);
            STG2((u64)dst1 + 48, acc1[6], acc1[7]);
            BART(tbar);
        }
    }
    __syncthreads();     // xw0 slab globally visible CTA-wide; staging dead

    // =========== PHASE 2: split weights into bf16 hi/lo swizzled tiles =====
    {
        const float* srcs[3] = { Whh0, Wih1, Whh1 };
#pragma unroll
        for (int m = 0; m < 3; m++) {
            char* hiT = smem + SM_W + (2 * m) * WTILE2;
            char* loT = hiT + WTILE2;
            const float* src = srcs[m];
            for (int idx = tid; idx < HID * HID; idx += 512) {
                int n = idx >> 7, k = idx & 127;
                float wv = src[idx];
                __nv_bfloat16 h = __float2bfloat16(wv);
                float hf = __bfloat162float(h);
                __nv_bfloat16 l = __float2bfloat16(wv - hf);
                uint32_t off = wtile_off2(n, k);
                *(__nv_bfloat16*)(hiT + off) = h;
                *(__nv_bfloat16*)(loT + off) = l;
            }
        }
        float* b1s = (float*)(smem + SM_B1);
        __syncthreads();                 // b0s fully consumed before overwrite
        if (tid < HID) b1s[tid] = bih1[tid] + bhh1[tid];
    }
    __syncthreads();

    // =========== PHASE 3: recurrence ========================================
    const uint32_t sb = smaddr(smem);
    const int xr  = lane & 7;
    const int kbB = (lane >> 3) & 1;
    const int rowB = (lane & 7) + ((lane >> 4) << 3);
    const int kbA = (lane >> 4) & 1;
    const int rowA = (lane & 7) + (((lane >> 3) & 1) << 3);
    const int gr = lane >> 2, m2 = (lane & 3) * 2;

    const uint32_t w0h = sb + 0 * WTILE2 + (uint32_t)(u * 32 + rowB) * WROWB;
    const uint32_t w0l = sb + 1 * WTILE2 + (uint32_t)(u * 32 + rowB) * WROWB;
    const uint32_t w1h = sb + 2 * WTILE2 + (uint32_t)(u * 32 + rowB) * WROWB;
    const uint32_t w1l = sb + 3 * WTILE2 + (uint32_t)(u * 32 + rowB) * WROWB;
    const uint32_t w2h = sb + 4 * WTILE2 + (uint32_t)(u * 32 + rowB) * WROWB;
    const uint32_t w2l = sb + 5 * WTILE2 + (uint32_t)(u * 32 + rowB) * WROWB;

    const uint32_t hbuf = sb + SM_HX + (uint32_t)q * 8192;
    const uint32_t hA1 = hbuf + (uint32_t)rowA * WROWB;
    const uint32_t hA0 = hA1 + 4096;
    const uint32_t hw = hbuf + (uint32_t)gr * WROWB + (uint32_t)m2 * 2;

    const float* b1s = (const float*)(smem + SM_B1);
    const int barid = 1 + q;

    const int rowbase = blockIdx.x * 64 + q * 16;
    const float* xb0 = g_xw0 + (size_t)(rowbase + gr) * T_STEPS * HID;
    const float* xb8 = xb0 + (size_t)8 * T_STEPS * HID;

    float d0[4][4], d1[4][4];
#pragma unroll
    for (int nb = 0; nb < 4; nb++) {
        const int cg = u * 32 + nb * 8 + m2;
        float2 p0 = *(const float2*)(xb0 + cg);   // x(t=0)
        float2 p8 = *(const float2*)(xb8 + cg);
        d0[nb][0] = p0.x; d0[nb][1] = p0.y; d0[nb][2] = p8.x; d0[nb][3] = p8.y;
#pragma unroll
        for (int qq = 0; qq < 4; qq++) d1[nb][qq] = 0.0f;
    }

#pragma unroll 1
    for (int t = 0; t < T_STEPS; t++) {
        // ---- epi0: h0(t) = tanh(d0) -> publish to quad buffer ----
#pragma unroll
        for (int nb = 0; nb < 4; nb++) {
            float v0 = ftanh(d0[nb][0]);
            float v1 = ftanh(d0[nb][1]);
            float v2 = ftanh(d0[nb][2]);
            float v3 = ftanh(d0[nb][3]);
            uint32_t hi0, lo0, hi8, lo8;
            cvt_pair(v0, v1, hi0, lo0);
            cvt_pair(v2, v3, hi8, lo8);
            uint32_t off = (uint32_t)((((u * 4 + nb)) ^ gr) << 4);
            STS32(hw + off,        hi0);
            STS32(hw + off + 2048, hi8);
            STS32(hw + off + 4096, lo0);
            STS32(hw + off + 6144, lo8);
        }
        BARQ(barid);                 // h0(t) visible to quad

        // ---- layer1 term 1: d1 += h0(t) @ Wih1^T ----
        gemm3q(d1, hA1, hA0, w1h, w1l, kbA, kbB, xr);

        // ---- next-step layer0: d0 = x(t+1) + h0(t) @ Whh0^T ----
        if (t + 1 < T_STEPS) {
#pragma unroll
            for (int nb = 0; nb < 4; nb++) {
                const int cg = u * 32 + nb * 8 + m2;
                float2 p0 = *(const float2*)(xb0 + (size_t)(t + 1) * HID + cg);
                float2 p8 = *(const float2*)(xb8 + (size_t)(t + 1) * HID + cg);
                d0[nb][0] = p0.x; d0[nb][1] = p0.y; d0[nb][2] = p8.x; d0[nb][3] = p8.y;
            }
            gemm3q(d0, hA1, hA0, w0h, w0l, kbA, kbB, xr);
        }
        BARQ(barid);                 // h0 buffer consumed by all quad warps

        if (t + 1 < T_STEPS) {
            // ---- epi1: h1(t) = tanh(d1 + b1) -> publish ----
#pragma unroll
            for (int nb = 0; nb < 4; nb++) {
                const int cg = u * 32 + nb * 8 + m2;
                float2 bb = *(const float2*)(b1s + cg);
                float v0 = ftanh(d1[nb][0] + bb.x);
                float v1 = ftanh(d1[nb][1] + bb.y);
                float v2 = ftanh(d1[nb][2] + bb.x);
                float v3 = ftanh(d1[nb][3] + bb.y);
                uint32_t hi0, lo0, hi8, lo8;
                cvt_pair(v0, v1, hi0, lo0);
                cvt_pair(v2, v3, hi8, lo8);
                uint32_t off = (uint32_t)((((u * 4 + nb)) ^ gr) << 4);
                STS32(hw + off,        hi0);
                STS32(hw + off + 2048, hi8);
                STS32(hw + off + 4096, lo0);
                STS32(hw + off + 6144, lo8);
            }
            BARQ(barid);             // h1(t) visible

            // ---- start next step's W2 term: d1 = h1(t) @ Whh1^T ----
#pragma unroll
            for (int nb = 0; nb < 4; nb++)
#pragma unroll
                for (int qq = 0; qq < 4; qq++) d1[nb][qq] = 0.0f;
            gemm3q(d1, hA1, hA0, w2h, w2l, kbA, kbB, xr);
            BARQ(barid);             // h1 buffer consumed
        } else {
            // ---- FC head: out = tanh(d1 + b1) @ fc_w^T + fc_b ----
            float facc0[NCLS], facc1[NCLS];
#pragma unroll
            for (int cl = 0; cl < NCLS; cl++) { facc0[cl] = 0.0f; facc1[cl] = 0.0f; }
#pragma unroll
            for (int nb = 0; nb < 4; nb++) {
                const int cg = u * 32 + nb * 8 + m2;
                float2 bb = *(const float2*)(b1s + cg);
                float h00 = ftanh(d1[nb][0] + bb.x);
                float h01 = ftanh(d1[nb][1] + bb.y);
                float h80 = ftanh(d1[nb][2] + bb.x);
                float h81 = ftanh(d1[nb][3] + bb.y);
#pragma unroll
                for (int cl = 0; cl < NCLS; cl++) {
                    float2 fw = *(const float2*)(fcw + cl * HID + cg);
                    facc0[cl] += h00 * fw.x + h01 * fw.y;
                    facc1[cl] += h80 * fw.x + h81 * fw.y;
                }
            }
#pragma unroll
            for (int cl = 0; cl < NCLS; cl++) {
                facc0[cl] += __shfl_xor_sync(0xffffffff, facc0[cl], 1);
                facc0[cl] += __shfl_xor_sync(0xffffffff, facc0[cl], 2);
                facc1[cl] += __shfl_xor_sync(0xffffffff, facc1[cl], 1);
                facc1[cl] += __shfl_xor_sync(0xffffffff, facc1[cl], 2);
            }
            // quad-level reduce through the (free) exchange buffer
            float* part = (float*)(smem + SM_HX + q * 8192);  // [u][16 rows][10]
            if ((lane & 3) == 0) {
#pragma unroll
                for (int cl = 0; cl < NCLS; cl++) {
                    part[(u * 16 + gr) * NCLS + cl]     = facc0[cl];
                    part[(u * 16 + gr + 8) * NCLS + cl] = facc1[cl];
                }
            }
            BARQ(barid);
            if (u == 0 && lane < 16) {
                const int grow = rowbase + lane;
#pragma unroll
                for (int cl = 0; cl < NCLS; cl++) {
                    float s = part[lane * NCLS + cl]
                            + part[(16 + lane) * NCLS + cl]
                            + part[(32 + lane) * NCLS + cl]
                            + part[(48 + lane) * NCLS + cl];
                    out[(size_t)grow * NCLS + cl] = s + fcb[cl];
                }
            }
        }
    }
}

// ---------------------------------------------------------------------------
extern "C" void kernel_launch(void* const* d_in, const int* in_sizes, int n_in,
                              void* d_out, int out_size) {
    const float* x    = (const float*)d_in[0];
    const float* Wih0 = (const float*)d_in[1];
    const float* Whh0 = (const float*)d_in[2];
    const float* bih0 = (const float*)d_in[3];
    const float* bhh0 = (const float*)d_in[4];
    const float* Wih1 = (const float*)d_in[5];
    const float* Whh1 = (const float*)d_in[6];
    const float* bih1 = (const float*)d_in[7];
    const float* bhh1 = (const float*)d_in[8];
    const float* fcw  = (const float*)d_in[9];
    const float* fcb  = (const float*)d_in[10];
    float* out = (float*)d_out;

    cudaFuncSetAttribute(rnn_fused_kernel,
                         cudaFuncAttributeMaxDynamicSharedMemorySize, SMEM_TOTAL);

    rnn_fused_kernel<<<BATCH / 64, 512, SMEM_TOTAL>>>(
        x, Wih0, bih0, bhh0, Whh0, Wih1, Whh1, bih1, bhh1, fcw, fcb, out);
}